// round 14
// baseline (speedup 1.0000x reference)
#include <cuda_runtime.h>
#include <cuda_fp16.h>
#include <math.h>
#include <float.h>
#include <stdint.h>

// Problem-fixed shapes: z [B,D], W [C,D], out [B,C]
#define Bq 4096
#define Dq 2048
#define Cq 1000
#define Nsup (Bq + Cq)   // 5096, supports ordered [W; z]
#define KMAX 128
#define NTHR 256
#define BCAP 5096        // per-class bucket capacity (worst case)
#define PSZ ((size_t)Nsup * Cq)

// ---------------- scratch (static device globals; no allocation) ----------------
__device__ float g_P[2 * Nsup * Cq];      // 40.8 MB: two split-K partial buffers
__device__ float g_invn[Nsup];
__device__ int   g_cnt[Cq];
__device__ float g_bktE[Cq * BCAP];       // per-class entropy buckets
__device__ int   g_bktI[Cq * BCAP];
__device__ int   g_selidx[Cq * KMAX];
__device__ int   g_selcnt[Cq];
__device__ __half g_Ah[Nsup * Dq], g_Am[Nsup * Dq];   // fp16 limb splits of [W; z]
__device__ __half g_Th[Cq * Dq];                      // fp16 high limb of weights^T

// ==================== mma.sync fp16 multi-pair GEMM (C = A*B^T) =================
// MODE 3: C = Ah*Bh^T + Ah*Bm^T + Am*Bh^T   (logits, ~fp32 accuracy)
// MODE 1: C = Ah*Bh^T                        (final, both operands single-limb)
#define BKC   32                       // K per chunk
#define NCH   (Dq / BKC)               // 64
#define TPADH 40                       // padded half-stride: 80 B rows, conflict-free
#define TROWB (TPADH * 2)              // 80 B per row
#define TILEA (128 * TROWB)            // 10240 B (A tile, always 128 rows)

__device__ __forceinline__ uint32_t smem_u32(const void* p) {
    uint32_t a;
    asm("{ .reg .u64 t; cvta.to.shared.u64 t, %1; cvt.u32.u64 %0, t; }" : "=r"(a) : "l"(p));
    return a;
}
__device__ __forceinline__ void cp16(uint32_t dst, const void* src, uint32_t srcsize) {
    asm volatile("cp.async.cg.shared.global [%0], [%1], 16, %2;"
                 :: "r"(dst), "l"(src), "r"(srcsize) : "memory");
}
__device__ __forceinline__ void mma16816(float* c, const uint32_t* a, const uint32_t* b) {
    asm volatile("mma.sync.aligned.m16n8k16.row.col.f32.f16.f16.f32 "
                 "{%0,%1,%2,%3}, {%4,%5,%6,%7}, {%8,%9}, {%0,%1,%2,%3};"
                 : "+f"(c[0]), "+f"(c[1]), "+f"(c[2]), "+f"(c[3])
                 : "r"(a[0]), "r"(a[1]), "r"(a[2]), "r"(a[3]), "r"(b[0]), "r"(b[1]));
}
__device__ __forceinline__ void ldsm4(uint32_t* r, uint32_t addr) {
    asm volatile("ldmatrix.sync.aligned.m8n8.x4.shared.b16 {%0,%1,%2,%3}, [%4];"
                 : "=r"(r[0]), "=r"(r[1]), "=r"(r[2]), "=r"(r[3]) : "r"(addr));
}

// TN = tile width (64 or 128). Warp grid: 2 (m) x 4 (n); warp covers 64 x TN/4.
template<int MODE, int TN, bool SPLITK>
__global__ __launch_bounds__(256, 2) void gemm_k(
    const __half* __restrict__ Ah, const __half* __restrict__ Am,
    const __half* __restrict__ Bh, const __half* __restrict__ Bm,
    float* __restrict__ C, int M, int N)
{
    constexpr int LA    = (MODE == 3) ? 2 : 1;        // limbs per operand
    constexpr int TILEBN = TN * TROWB;                // B tile bytes
    constexpr uint32_t offAh = 0, offAm = TILEA;
    constexpr uint32_t offBh = LA * TILEA;
    constexpr uint32_t offBm = LA * TILEA + TILEBN;
    constexpr uint32_t STAGE = LA * (TILEA + TILEBN);
    constexpr int nA  = 512 * LA;                     // 16B transfers for A tiles
    constexpr int nB  = TN * 4 * LA;                  // 16B transfers for B tiles
    constexpr int NTR = nA + nB;
    constexpr int NTW = TN / 4;                       // warp n-extent (16 or 32)
    constexpr int NP  = NTW / 16;                     // ldmatrix n16-pairs (1 or 2)
    constexpr int NT  = NTW / 8;                      // n8 tiles per warp (2 or 4)

    extern __shared__ char smem[];
    const uint32_t sbase = smem_u32(smem);
    const int tid = threadIdx.x;
    const int wid = tid >> 5;
    const int lane = tid & 31;
    const int mBase = blockIdx.y * 128;
    const int nBase = blockIdx.x * TN;
    const int wm = (wid & 1) * 64;
    const int wn = (wid >> 1) * NTW;
    const int NCHL = SPLITK ? (NCH / 2) : NCH;
    const int c0 = SPLITK ? blockIdx.z * NCHL : 0;
    if (SPLITK) C += (size_t)blockIdx.z * PSZ;        // per-half partial buffer

    // ldmatrix lane->address components (byte offsets within a tile)
    const int aRow = lane & 15;
    const int aKB  = (lane >> 4) * 16;
    const int bG   = lane >> 3;
    const int bRow = (lane & 7) + ((bG >> 1) << 3);
    const int bKB  = (bG & 1) * 16;

    float acc[4][NT][4];
#pragma unroll
    for (int i = 0; i < 4; i++)
#pragma unroll
        for (int j = 0; j < NT; j++)
#pragma unroll
            for (int q = 0; q < 4; q++) acc[i][j][q] = 0.f;

    auto load_chunk = [&](int c, int stage) {
        const uint32_t stBase = sbase + stage * STAGE;
#pragma unroll
        for (int i0 = 0; i0 < NTR; i0 += 256) {
            const int i = i0 + tid;
            const bool isA = i < nA;
            const int j = isA ? i : i - nA;
            const int limb = isA ? (j >> 9) : (j / (TN * 4));
            const int within = isA ? (j & 511) : (j % (TN * 4));
            const int r = within >> 2, s = within & 3;
            const int rb = (isA ? mBase : nBase) + r;
            const int bound = isA ? M : N;
            const uint32_t off = isA ? (limb ? offAm : offAh) : (limb ? offBm : offBh);
            const __half* src = isA ? (limb ? Am : Ah) : (limb ? Bm : Bh);
            const uint32_t dst = stBase + off + r * TROWB + s * 16;
            cp16(dst, src + (size_t)rb * Dq + c * BKC + s * 8, (rb < bound) ? 16u : 0u);
        }
        asm volatile("cp.async.commit_group;" ::: "memory");
    };

    load_chunk(c0, 0);

    for (int cc = 0; cc < NCHL; cc++) {
        asm volatile("cp.async.wait_group 0;" ::: "memory");
        __syncthreads();                       // buf cc&1 ready AND prior consumers done
        if (cc + 1 < NCHL) load_chunk(c0 + cc + 1, (cc + 1) & 1);   // overlaps consume

        const uint32_t st = sbase + (cc & 1) * STAGE;
        const uint32_t aH = st + offAh;
        const uint32_t aM = st + offAm;
        const uint32_t bH = st + offBh;
        const uint32_t bM = st + offBm;

#pragma unroll
        for (int k16 = 0; k16 < BKC / 16; k16++) {
            const int kOff = k16 * 32;
            uint32_t bh[NT][2], bm[NT][2];
#pragma unroll
            for (int p = 0; p < NP; p++) {
                const uint32_t bOff = (uint32_t)(wn + p * 16 + bRow) * TROWB + kOff + bKB;
                ldsm4(&bh[p * 2][0], bH + bOff);
                if (MODE == 3) ldsm4(&bm[p * 2][0], bM + bOff);
            }
#pragma unroll
            for (int mt = 0; mt < 4; mt++) {
                const uint32_t aOff = (uint32_t)(wm + mt * 16 + aRow) * TROWB + kOff + aKB;
                uint32_t ah[4], am[4];
                ldsm4(ah, aH + aOff);
                if (MODE == 3) ldsm4(am, aM + aOff);
#pragma unroll
                for (int nt = 0; nt < NT; nt++) {
                    mma16816(acc[mt][nt], ah, bh[nt]);
                    if (MODE == 3) {
                        mma16816(acc[mt][nt], ah, bm[nt]);
                        mma16816(acc[mt][nt], am, bh[nt]);
                    }
                }
            }
        }
    }

    // epilogue: plain stores (split-K halves go to separate buffers)
#pragma unroll
    for (int mt = 0; mt < 4; mt++) {
        const int row0 = mBase + wm + mt * 16 + (lane >> 2);
#pragma unroll
        for (int nt = 0; nt < NT; nt++) {
            const int col0 = nBase + wn + nt * 8 + (lane & 3) * 2;
            if (col0 < N) {
                if (row0 < M)
                    *(float2*)&C[(size_t)row0 * N + col0] =
                        make_float2(acc[mt][nt][0], acc[mt][nt][1]);
                if (row0 + 8 < M)
                    *(float2*)&C[(size_t)(row0 + 8) * N + col0] =
                        make_float2(acc[mt][nt][2], acc[mt][nt][3]);
            }
        }
    }
}

#define GSMEM3 (2 * 2 * (TILEA + 64 * TROWB))     // MODE3, TN=64: 61440
#define GSMEM1 (2 * (TILEA + 128 * TROWB))        // MODE1, TN=128: 40960

// -- fused: split fp32 -> 2 fp16 limbs + inv L2 norm + zero class counters -------
__global__ __launch_bounds__(NTHR) void split_norm(
    const float* __restrict__ z, const float* __restrict__ W,
    __half* __restrict__ Ah, __half* __restrict__ Am, float* __restrict__ invn,
    int* __restrict__ cnt)
{
    const int r = blockIdx.x;   // support index: [0,Cq) = W, [Cq,Nsup) = z
    const float* src = (r < Cq) ? (W + (size_t)r * Dq) : (z + (size_t)(r - Cq) * Dq);
    const int tid = threadIdx.x;

    if (r == 0) for (int i = tid; i < Cq; i += NTHR) cnt[i] = 0;

    float ss = 0.f;
    const float4* src4 = (const float4*)src;
#pragma unroll
    for (int j = 0; j < Dq / (NTHR * 4); j++) {
        const int i4 = tid + j * NTHR;
        float4 x = src4[i4];
        const int i = i4 * 4;
        __half h0 = __float2half_rn(x.x), h1 = __float2half_rn(x.y);
        __half h2 = __float2half_rn(x.z), h3 = __float2half_rn(x.w);
        Ah[(size_t)r * Dq + i + 0] = h0; Ah[(size_t)r * Dq + i + 1] = h1;
        Ah[(size_t)r * Dq + i + 2] = h2; Ah[(size_t)r * Dq + i + 3] = h3;
        Am[(size_t)r * Dq + i + 0] = __float2half_rn(x.x - __half2float(h0));
        Am[(size_t)r * Dq + i + 1] = __float2half_rn(x.y - __half2float(h1));
        Am[(size_t)r * Dq + i + 2] = __float2half_rn(x.z - __half2float(h2));
        Am[(size_t)r * Dq + i + 3] = __float2half_rn(x.w - __half2float(h3));
        ss += x.x * x.x + x.y * x.y + x.z * x.z + x.w * x.w;
    }
    __shared__ float red[NTHR];
    red[tid] = ss; __syncthreads();
    for (int s = NTHR / 2; s > 0; s >>= 1) {
        if (tid < s) red[tid] += red[tid + s];
        __syncthreads();
    }
    if (tid == 0) invn[r] = 1.0f / fmaxf(sqrtf(red[0]), 1e-12f);
}

// -- warp-per-row: sum split-K partials, entropy + argmax + bucket scatter -------
__global__ __launch_bounds__(NTHR) void row_entropy_scatter(
    const float* __restrict__ P0, const float* __restrict__ P1,
    int* __restrict__ cnt, float* __restrict__ bktE, int* __restrict__ bktI)
{
    const int row = blockIdx.x * 8 + (threadIdx.x >> 5);
    const int lane = threadIdx.x & 31;
    const float4* p0 = (const float4*)(P0 + (size_t)row * Cq);
    const float4* p1 = (const float4*)(P1 + (size_t)row * Cq);

    float4 v[8];
    float m = -FLT_MAX; int mi = 0x7fffffff;
#pragma unroll
    for (int j = 0; j < 8; j++) {
        const int i4 = lane + j * 32;
        if (i4 < 250) {
            float4 a = p0[i4], b = p1[i4];
            v[j] = make_float4(a.x + b.x, a.y + b.y, a.z + b.z, a.w + b.w);
            const int gi = i4 * 4;
            if (v[j].x > m) { m = v[j].x; mi = gi; }
            if (v[j].y > m) { m = v[j].y; mi = gi + 1; }
            if (v[j].z > m) { m = v[j].z; mi = gi + 2; }
            if (v[j].w > m) { m = v[j].w; mi = gi + 3; }
        } else {
            v[j] = make_float4(-FLT_MAX, -FLT_MAX, -FLT_MAX, -FLT_MAX);
        }
    }
#pragma unroll
    for (int o = 16; o > 0; o >>= 1) {
        float m2 = __shfl_xor_sync(0xffffffffu, m, o);
        int   i2 = __shfl_xor_sync(0xffffffffu, mi, o);
        if (m2 > m || (m2 == m && i2 < mi)) { m = m2; mi = i2; }
    }

    float s1 = 0.f, s2 = 0.f;
#pragma unroll
    for (int j = 0; j < 8; j++) {
        if (lane + j * 32 < 250) {
            float d0 = v[j].x - m, d1 = v[j].y - m, d2 = v[j].z - m, d3 = v[j].w - m;
            float e0 = expf(d0), e1 = expf(d1), e2 = expf(d2), e3 = expf(d3);
            s1 += e0 + e1 + e2 + e3;
            s2 += e0 * d0 + e1 * d1 + e2 * d2 + e3 * d3;
        }
    }
#pragma unroll
    for (int o = 16; o > 0; o >>= 1) {
        s1 += __shfl_xor_sync(0xffffffffu, s1, o);
        s2 += __shfl_xor_sync(0xffffffffu, s2, o);
    }

    if (lane == 0) {
        float e = logf(s1) - s2 / s1;
        int pos = atomicAdd(&cnt[mi], 1);
        bktE[(size_t)mi * BCAP + pos] = e;
        bktI[(size_t)mi * BCAP + pos] = row;
    }
}

// ---- per-class K smallest, warp-per-class, no mutation (ascending emit) --------
__global__ __launch_bounds__(NTHR) void select_topk(
    const int* __restrict__ cnt, const float* __restrict__ bktE,
    const int* __restrict__ bktI, const int* __restrict__ pK,
    int* __restrict__ selidx, int* __restrict__ selcnt)
{
    const int c = blockIdx.x * (NTHR / 32) + (threadIdx.x >> 5);
    if (c >= Cq) return;
    const int lane = threadIdx.x & 31;
    int K = *pK; if (K > KMAX) K = KMAX;
    const int n = cnt[c];
    const int take = (n < K) ? n : K;
    const float* E = bktE + (size_t)c * BCAP;
    const int*   I = bktI + (size_t)c * BCAP;

    float prevE = -FLT_MAX; int prevI = -1;
    for (int t = 0; t < take; t++) {
        float bv = FLT_MAX; int bk = 0x7fffffff;
        for (int i = lane; i < n; i += 32) {
            float v = E[i]; int key = I[i];
            bool gt_prev = (v > prevE) || (v == prevE && key > prevI);
            if (gt_prev && (v < bv || (v == bv && key < bk))) { bv = v; bk = key; }
        }
#pragma unroll
        for (int o = 16; o > 0; o >>= 1) {
            float v2 = __shfl_down_sync(0xffffffffu, bv, o);
            int   k2 = __shfl_down_sync(0xffffffffu, bk, o);
            if (v2 < bv || (v2 == bv && k2 < bk)) { bv = v2; bk = k2; }
        }
        bv = __shfl_sync(0xffffffffu, bv, 0);
        bk = __shfl_sync(0xffffffffu, bk, 0);
        if (lane == 0) selidx[c * KMAX + t] = bk;
        prevE = bv; prevI = bk;
    }
    if (lane == 0) selcnt[c] = take;
}

// ----- build normalized prototypes, emit fp16 high limb of weights^T ------------
__global__ __launch_bounds__(NTHR) void build_weights(
    const float* __restrict__ W, const float* __restrict__ z,
    const float* __restrict__ invn, const int* __restrict__ selidx,
    const int* __restrict__ selcnt, __half* __restrict__ Th)
{
    const int c = blockIdx.x;
    const int n = selcnt[c];
    const int tid = threadIdx.x;
    float acc[Dq / NTHR];
#pragma unroll
    for (int j = 0; j < Dq / NTHR; j++) acc[j] = 0.f;

    for (int t = 0; t < n; t++) {
        int idx = selidx[c * KMAX + t];
        float s = invn[idx];
        const float* row = (idx < Cq) ? (W + (size_t)idx * Dq) : (z + (size_t)(idx - Cq) * Dq);
#pragma unroll
        for (int j = 0; j < Dq / NTHR; j++) acc[j] += s * row[tid + j * NTHR];
    }

    float ss = 0.f;
#pragma unroll
    for (int j = 0; j < Dq / NTHR; j++) ss += acc[j] * acc[j];
    __shared__ float red[NTHR];
    red[tid] = ss; __syncthreads();
    for (int s = NTHR / 2; s > 0; s >>= 1) {
        if (tid < s) red[tid] += red[tid + s];
        __syncthreads();
    }
    const float inv = 1.0f / fmaxf(sqrtf(red[0]), 1e-12f);
#pragma unroll
    for (int j = 0; j < Dq / NTHR; j++)
        Th[(size_t)c * Dq + tid + j * NTHR] = __float2half_rn(acc[j] * inv);
}

// --------------------------------- launch ---------------------------------------
extern "C" void kernel_launch(void* const* d_in, const int* in_sizes, int n_in,
                              void* d_out, int out_size)
{
    const float* z = (const float*)d_in[0];
    const float* W = (const float*)d_in[1];
    const int* pK  = (const int*)d_in[2];
    float* out = (float*)d_out;

    float *P, *invn, *bktE;
    int *cnt, *bktI, *selidx, *selcnt;
    __half *Ah, *Am, *Th;
    cudaGetSymbolAddress((void**)&P, g_P);
    cudaGetSymbolAddress((void**)&invn, g_invn);
    cudaGetSymbolAddress((void**)&cnt, g_cnt);
    cudaGetSymbolAddress((void**)&bktE, g_bktE);
    cudaGetSymbolAddress((void**)&bktI, g_bktI);
    cudaGetSymbolAddress((void**)&selidx, g_selidx);
    cudaGetSymbolAddress((void**)&selcnt, g_selcnt);
    cudaGetSymbolAddress((void**)&Ah, g_Ah);
    cudaGetSymbolAddress((void**)&Am, g_Am);
    cudaGetSymbolAddress((void**)&Th, g_Th);

    cudaFuncSetAttribute((const void*)gemm_k<3, 64, true>,
                         cudaFuncAttributeMaxDynamicSharedMemorySize, GSMEM3);
    cudaFuncSetAttribute((const void*)gemm_k<1, 128, false>,
                         cudaFuncAttributeMaxDynamicSharedMemorySize, GSMEM1);

    // 0) limb split of [W; z], inverse norms, zero counters
    split_norm<<<Nsup, NTHR>>>(z, W, Ah, Am, invn, cnt);

    // 1) merged logits: 128x64 tiles, split-K=2 -> 1280 CTAs (fine-grain waves)
    gemm_k<3, 64, true><<<dim3(16, 40, 2), 256, GSMEM3>>>(Ah, Am, Ah, Am, P, Nsup, Cq);

    // 2) warp-per-row: sum partials, entropy + argmax + per-class bucket scatter
    row_entropy_scatter<<<Nsup / 8, NTHR>>>(P, P + PSZ, cnt, bktE, bktI);

    // 3) per-class selection (warp per class, read-only, ascending emit)
    select_topk<<<(Cq + (NTHR / 32) - 1) / (NTHR / 32), NTHR>>>(cnt, bktE, bktI, pK,
                                                               selidx, selcnt);

    // 4) prototypes (fp16 high limb only)
    build_weights<<<Cq, NTHR>>>(W, z, invn, selidx, selcnt, Th);

    // 5) out = z @ weights   (single-pair fp16, 128x128 tiles, <1 wave)
    gemm_k<1, 128, false><<<dim3(8, 32), 256, GSMEM1>>>(Ah + (size_t)Cq * Dq,
                                                        Am + (size_t)Cq * Dq,
                                                        Th, Th, out, Bq, Cq);
}

// round 16
// speedup vs baseline: 1.1104x; 1.1104x over previous
#include <cuda_runtime.h>
#include <cuda_fp16.h>
#include <math.h>
#include <float.h>
#include <stdint.h>

// Problem-fixed shapes: z [B,D], W [C,D], out [B,C]
#define Bq 4096
#define Dq 2048
#define Cq 1000
#define Nsup (Bq + Cq)   // 5096, supports ordered [W; z]
#define KMAX 128
#define NTHR 256
#define BCAP 5096        // per-class bucket capacity (worst case)
#define PSZ ((size_t)Nsup * Cq)
#define SPLITK_N 4

// ---------------- scratch (static device globals; no allocation) ----------------
__device__ float g_P[SPLITK_N * Nsup * Cq];   // 81.6 MB: split-K partial buffers
__device__ float g_invn[Nsup];
__device__ int   g_cnt[Cq];
__device__ float g_bktE[Cq * BCAP];           // per-class entropy buckets
__device__ int   g_bktI[Cq * BCAP];
__device__ int   g_selidx[Cq * KMAX];
__device__ int   g_selcnt[Cq];
__device__ __half g_Ah[Nsup * Dq], g_Am[Nsup * Dq];   // fp16 limb splits of [W; z]
__device__ __half g_Th[Cq * Dq];                      // fp16 high limb of weights^T

// ==================== mma.sync fp16 multi-pair GEMM (C = A*B^T) =================
// MODE 3: C = Ah*Bh^T + Ah*Bm^T + Am*Bh^T   (logits, ~fp32 accuracy)
// MODE 1: C = Ah*Bh^T                        (final, both operands single-limb)
#define BKC   32                       // K per chunk
#define NCH   (Dq / BKC)               // 64
#define TPADH 40                       // padded half-stride: 80 B rows, conflict-free
#define TROWB (TPADH * 2)              // 80 B per row
#define TILEB (128 * TROWB)            // 10240 B
#define STAGE4 (4 * TILEB)             // 40960 B (Ah, Am, Bh, Bm)
#define GSMEM (2 * STAGE4)             // 81920 B -> 2 CTAs/SM

__device__ __forceinline__ uint32_t smem_u32(const void* p) {
    uint32_t a;
    asm("{ .reg .u64 t; cvta.to.shared.u64 t, %1; cvt.u32.u64 %0, t; }" : "=r"(a) : "l"(p));
    return a;
}
__device__ __forceinline__ void cp16(uint32_t dst, const void* src, uint32_t srcsize) {
    asm volatile("cp.async.cg.shared.global [%0], [%1], 16, %2;"
                 :: "r"(dst), "l"(src), "r"(srcsize) : "memory");
}
__device__ __forceinline__ void mma16816(float* c, const uint32_t* a, const uint32_t* b) {
    asm volatile("mma.sync.aligned.m16n8k16.row.col.f32.f16.f16.f32 "
                 "{%0,%1,%2,%3}, {%4,%5,%6,%7}, {%8,%9}, {%0,%1,%2,%3};"
                 : "+f"(c[0]), "+f"(c[1]), "+f"(c[2]), "+f"(c[3])
                 : "r"(a[0]), "r"(a[1]), "r"(a[2]), "r"(a[3]), "r"(b[0]), "r"(b[1]));
}
__device__ __forceinline__ void ldsm4(uint32_t* r, uint32_t addr) {
    asm volatile("ldmatrix.sync.aligned.m8n8.x4.shared.b16 {%0,%1,%2,%3}, [%4];"
                 : "=r"(r[0]), "=r"(r[1]), "=r"(r[2]), "=r"(r[3]) : "r"(addr));
}

template<int MODE, bool SPLITK>
__global__ __launch_bounds__(256, 2) void gemm_k(
    const __half* __restrict__ Ah, const __half* __restrict__ Am,
    const __half* __restrict__ Bh, const __half* __restrict__ Bm,
    float* __restrict__ C, int M, int N)
{
    extern __shared__ char smem[];
    const uint32_t sbase = smem_u32(smem);
    const int tid = threadIdx.x;
    const int wid = tid >> 5;
    const int lane = tid & 31;
    const int mBase = blockIdx.y * 128;
    const int nBase = blockIdx.x * 128;
    const int wm = (wid & 1) * 64;
    const int wn = (wid >> 1) * 32;
    const int NCHL = SPLITK ? (NCH / SPLITK_N) : NCH;
    const int c0 = SPLITK ? blockIdx.z * NCHL : 0;
    if (SPLITK) C += (size_t)blockIdx.z * PSZ;     // per-slice partial buffer

    const __half* srcs[4] = { Ah, Am, Bh, Bm };

    // ldmatrix lane->address components (byte offsets within a tile)
    const int aRow = lane & 15;                         // rows 0..15 of m16 tile
    const int aKB  = (lane >> 4) * 16;                  // +8 halves = +16 B for k8-15
    const int bG   = lane >> 3;
    const int bRow = (lane & 7) + ((bG >> 1) << 3);     // rows 0..15 of n16 pair
    const int bKB  = (bG & 1) * 16;

    float acc[4][4][4];
#pragma unroll
    for (int i = 0; i < 4; i++)
#pragma unroll
        for (int j = 0; j < 4; j++)
#pragma unroll
            for (int q = 0; q < 4; q++) acc[i][j][q] = 0.f;

    // chunk loader: tiles {Ah[,Am],Bh[,Bm]} x 128 rows x 64 B
    auto load_chunk = [&](int c, int stage) {
        const uint32_t stBase = sbase + stage * STAGE4;
#pragma unroll
        for (int i = 0; i < 8; i++) {
            const int t = i >> 1;                   // tile 0..3 (uniform per i)
            if (MODE == 1 && (t == 1 || t == 3)) continue;   // only Ah, Bh
            const int idx = tid + i * 256;          // 0..2047
            const int r = (idx >> 2) & 127;         // row 0..127
            const int s = idx & 3;                  // 16B segment 0..3
            const int rb = ((t < 2) ? mBase : nBase) + r;
            const int bound = (t < 2) ? M : N;
            const uint32_t dst = stBase + t * TILEB + r * TROWB + s * 16;
            const __half* src = srcs[t] + (size_t)rb * Dq + c * BKC + s * 8;
            cp16(dst, src, (rb < bound) ? 16u : 0u);
        }
        asm volatile("cp.async.commit_group;" ::: "memory");
    };

    load_chunk(c0, 0);

    for (int cc = 0; cc < NCHL; cc++) {
        if (cc + 1 < NCHL) {
            load_chunk(c0 + cc + 1, (cc + 1) & 1);
            asm volatile("cp.async.wait_group 1;" ::: "memory");
        } else {
            asm volatile("cp.async.wait_group 0;" ::: "memory");
        }
        __syncthreads();

        const uint32_t st = sbase + (cc & 1) * STAGE4;
        const uint32_t aH = st;
        const uint32_t aM = st + TILEB;
        const uint32_t bH = st + 2 * TILEB;
        const uint32_t bM = st + 3 * TILEB;

#pragma unroll
        for (int k16 = 0; k16 < BKC / 16; k16++) {
            const int kOff = k16 * 32;              // 16 halves = 32 B
            uint32_t bh[4][2], bm[4][2];
#pragma unroll
            for (int p = 0; p < 2; p++) {           // two n16 pairs cover nt 0..3
                const uint32_t bOff = (uint32_t)(wn + p * 16 + bRow) * TROWB + kOff + bKB;
                ldsm4(&bh[p * 2][0], bH + bOff);
                if (MODE == 3) ldsm4(&bm[p * 2][0], bM + bOff);
            }
#pragma unroll
            for (int mt = 0; mt < 4; mt++) {
                const uint32_t aOff = (uint32_t)(wm + mt * 16 + aRow) * TROWB + kOff + aKB;
                uint32_t ah[4], am[4];
                ldsm4(ah, aH + aOff);
                if (MODE == 3) ldsm4(am, aM + aOff);
#pragma unroll
                for (int nt = 0; nt < 4; nt++) {
                    mma16816(acc[mt][nt], ah, bh[nt]);
                    if (MODE == 3) {
                        mma16816(acc[mt][nt], ah, bm[nt]);
                        mma16816(acc[mt][nt], am, bh[nt]);
                    }
                }
            }
        }
        __syncthreads();
    }

    // epilogue: plain stores (split-K slices go to separate buffers)
#pragma unroll
    for (int mt = 0; mt < 4; mt++) {
        const int row0 = mBase + wm + mt * 16 + (lane >> 2);
#pragma unroll
        for (int nt = 0; nt < 4; nt++) {
            const int col0 = nBase + wn + nt * 8 + (lane & 3) * 2;
            if (col0 < N) {
                if (row0 < M)
                    *(float2*)&C[(size_t)row0 * N + col0] =
                        make_float2(acc[mt][nt][0], acc[mt][nt][1]);
                if (row0 + 8 < M)
                    *(float2*)&C[(size_t)(row0 + 8) * N + col0] =
                        make_float2(acc[mt][nt][2], acc[mt][nt][3]);
            }
        }
    }
}

// -- fused: split fp32 -> 2 fp16 limbs + inv L2 norm + zero class counters -------
__global__ __launch_bounds__(NTHR) void split_norm(
    const float* __restrict__ z, const float* __restrict__ W,
    __half* __restrict__ Ah, __half* __restrict__ Am, float* __restrict__ invn,
    int* __restrict__ cnt)
{
    const int r = blockIdx.x;   // support index: [0,Cq) = W, [Cq,Nsup) = z
    const float* src = (r < Cq) ? (W + (size_t)r * Dq) : (z + (size_t)(r - Cq) * Dq);
    const int tid = threadIdx.x;

    if (r == 0) for (int i = tid; i < Cq; i += NTHR) cnt[i] = 0;

    float ss = 0.f;
    const float4* src4 = (const float4*)src;
#pragma unroll
    for (int j = 0; j < Dq / (NTHR * 4); j++) {
        const int i4 = tid + j * NTHR;
        float4 x = src4[i4];
        const int i = i4 * 4;
        __half h0 = __float2half_rn(x.x), h1 = __float2half_rn(x.y);
        __half h2 = __float2half_rn(x.z), h3 = __float2half_rn(x.w);
        Ah[(size_t)r * Dq + i + 0] = h0; Ah[(size_t)r * Dq + i + 1] = h1;
        Ah[(size_t)r * Dq + i + 2] = h2; Ah[(size_t)r * Dq + i + 3] = h3;
        Am[(size_t)r * Dq + i + 0] = __float2half_rn(x.x - __half2float(h0));
        Am[(size_t)r * Dq + i + 1] = __float2half_rn(x.y - __half2float(h1));
        Am[(size_t)r * Dq + i + 2] = __float2half_rn(x.z - __half2float(h2));
        Am[(size_t)r * Dq + i + 3] = __float2half_rn(x.w - __half2float(h3));
        ss += x.x * x.x + x.y * x.y + x.z * x.z + x.w * x.w;
    }
    __shared__ float red[NTHR];
    red[tid] = ss; __syncthreads();
    for (int s = NTHR / 2; s > 0; s >>= 1) {
        if (tid < s) red[tid] += red[tid + s];
        __syncthreads();
    }
    if (tid == 0) invn[r] = 1.0f / fmaxf(sqrtf(red[0]), 1e-12f);
}

// -- warp-per-row: sum 4 split-K partials, entropy + argmax + bucket scatter -----
__global__ __launch_bounds__(NTHR) void row_entropy_scatter(
    const float* __restrict__ P,
    int* __restrict__ cnt, float* __restrict__ bktE, int* __restrict__ bktI)
{
    const int row = blockIdx.x * 8 + (threadIdx.x >> 5);
    const int lane = threadIdx.x & 31;
    const float4* p0 = (const float4*)(P + (size_t)row * Cq);
    const float4* p1 = (const float4*)(P + PSZ + (size_t)row * Cq);
    const float4* p2 = (const float4*)(P + 2 * PSZ + (size_t)row * Cq);
    const float4* p3 = (const float4*)(P + 3 * PSZ + (size_t)row * Cq);

    float4 v[8];
    float m = -FLT_MAX; int mi = 0x7fffffff;
#pragma unroll
    for (int j = 0; j < 8; j++) {
        const int i4 = lane + j * 32;
        if (i4 < 250) {
            float4 a = p0[i4], b = p1[i4], c = p2[i4], d = p3[i4];
            // fixed order: ((p0+p1)+p2)+p3 — deterministic
            v[j] = make_float4(((a.x + b.x) + c.x) + d.x, ((a.y + b.y) + c.y) + d.y,
                               ((a.z + b.z) + c.z) + d.z, ((a.w + b.w) + c.w) + d.w);
            const int gi = i4 * 4;
            if (v[j].x > m) { m = v[j].x; mi = gi; }
            if (v[j].y > m) { m = v[j].y; mi = gi + 1; }
            if (v[j].z > m) { m = v[j].z; mi = gi + 2; }
            if (v[j].w > m) { m = v[j].w; mi = gi + 3; }
        } else {
            v[j] = make_float4(-FLT_MAX, -FLT_MAX, -FLT_MAX, -FLT_MAX);
        }
    }
#pragma unroll
    for (int o = 16; o > 0; o >>= 1) {
        float m2 = __shfl_xor_sync(0xffffffffu, m, o);
        int   i2 = __shfl_xor_sync(0xffffffffu, mi, o);
        if (m2 > m || (m2 == m && i2 < mi)) { m = m2; mi = i2; }
    }

    float s1 = 0.f, s2 = 0.f;
#pragma unroll
    for (int j = 0; j < 8; j++) {
        if (lane + j * 32 < 250) {
            float d0 = v[j].x - m, d1 = v[j].y - m, d2 = v[j].z - m, d3 = v[j].w - m;
            float e0 = expf(d0), e1 = expf(d1), e2 = expf(d2), e3 = expf(d3);
            s1 += e0 + e1 + e2 + e3;
            s2 += e0 * d0 + e1 * d1 + e2 * d2 + e3 * d3;
        }
    }
#pragma unroll
    for (int o = 16; o > 0; o >>= 1) {
        s1 += __shfl_xor_sync(0xffffffffu, s1, o);
        s2 += __shfl_xor_sync(0xffffffffu, s2, o);
    }

    if (lane == 0) {
        float e = logf(s1) - s2 / s1;
        int pos = atomicAdd(&cnt[mi], 1);
        bktE[(size_t)mi * BCAP + pos] = e;
        bktI[(size_t)mi * BCAP + pos] = row;
    }
}

// ---- per-class K smallest, warp-per-class, no mutation (ascending emit) --------
__global__ __launch_bounds__(NTHR) void select_topk(
    const int* __restrict__ cnt, const float* __restrict__ bktE,
    const int* __restrict__ bktI, const int* __restrict__ pK,
    int* __restrict__ selidx, int* __restrict__ selcnt)
{
    const int c = blockIdx.x * (NTHR / 32) + (threadIdx.x >> 5);
    if (c >= Cq) return;
    const int lane = threadIdx.x & 31;
    int K = *pK; if (K > KMAX) K = KMAX;
    const int n = cnt[c];
    const int take = (n < K) ? n : K;
    const float* E = bktE + (size_t)c * BCAP;
    const int*   I = bktI + (size_t)c * BCAP;

    float prevE = -FLT_MAX; int prevI = -1;
    for (int t = 0; t < take; t++) {
        // min over entries strictly greater (lex) than (prevE, prevI)
        float bv = FLT_MAX; int bk = 0x7fffffff;
        for (int i = lane; i < n; i += 32) {
            float v = E[i]; int key = I[i];
            bool gt_prev = (v > prevE) || (v == prevE && key > prevI);
            if (gt_prev && (v < bv || (v == bv && key < bk))) { bv = v; bk = key; }
        }
#pragma unroll
        for (int o = 16; o > 0; o >>= 1) {
            float v2 = __shfl_down_sync(0xffffffffu, bv, o);
            int   k2 = __shfl_down_sync(0xffffffffu, bk, o);
            if (v2 < bv || (v2 == bv && k2 < bk)) { bv = v2; bk = k2; }
        }
        bv = __shfl_sync(0xffffffffu, bv, 0);
        bk = __shfl_sync(0xffffffffu, bk, 0);
        if (lane == 0) selidx[c * KMAX + t] = bk;
        prevE = bv; prevI = bk;
    }
    if (lane == 0) selcnt[c] = take;
}

// ----- build normalized prototypes, emit fp16 high limb of weights^T ------------
__global__ __launch_bounds__(NTHR) void build_weights(
    const float* __restrict__ W, const float* __restrict__ z,
    const float* __restrict__ invn, const int* __restrict__ selidx,
    const int* __restrict__ selcnt, __half* __restrict__ Th)
{
    const int c = blockIdx.x;
    const int n = selcnt[c];
    const int tid = threadIdx.x;
    float acc[Dq / NTHR];
#pragma unroll
    for (int j = 0; j < Dq / NTHR; j++) acc[j] = 0.f;

    for (int t = 0; t < n; t++) {
        int idx = selidx[c * KMAX + t];
        float s = invn[idx];
        const float* row = (idx < Cq) ? (W + (size_t)idx * Dq) : (z + (size_t)(idx - Cq) * Dq);
#pragma unroll
        for (int j = 0; j < Dq / NTHR; j++) acc[j] += s * row[tid + j * NTHR];
    }

    float ss = 0.f;
#pragma unroll
    for (int j = 0; j < Dq / NTHR; j++) ss += acc[j] * acc[j];
    __shared__ float red[NTHR];
    red[tid] = ss; __syncthreads();
    for (int s = NTHR / 2; s > 0; s >>= 1) {
        if (tid < s) red[tid] += red[tid + s];
        __syncthreads();
    }
    const float inv = 1.0f / fmaxf(sqrtf(red[0]), 1e-12f);
#pragma unroll
    for (int j = 0; j < Dq / NTHR; j++)
        Th[(size_t)c * Dq + tid + j * NTHR] = __float2half_rn(acc[j] * inv);
}

// --------------------------------- launch ---------------------------------------
extern "C" void kernel_launch(void* const* d_in, const int* in_sizes, int n_in,
                              void* d_out, int out_size)
{
    const float* z = (const float*)d_in[0];
    const float* W = (const float*)d_in[1];
    const int* pK  = (const int*)d_in[2];
    float* out = (float*)d_out;

    float *P, *invn, *bktE;
    int *cnt, *bktI, *selidx, *selcnt;
    __half *Ah, *Am, *Th;
    cudaGetSymbolAddress((void**)&P, g_P);
    cudaGetSymbolAddress((void**)&invn, g_invn);
    cudaGetSymbolAddress((void**)&cnt, g_cnt);
    cudaGetSymbolAddress((void**)&bktE, g_bktE);
    cudaGetSymbolAddress((void**)&bktI, g_bktI);
    cudaGetSymbolAddress((void**)&selidx, g_selidx);
    cudaGetSymbolAddress((void**)&selcnt, g_selcnt);
    cudaGetSymbolAddress((void**)&Ah, g_Ah);
    cudaGetSymbolAddress((void**)&Am, g_Am);
    cudaGetSymbolAddress((void**)&Th, g_Th);

    cudaFuncSetAttribute((const void*)gemm_k<3, true>,
                         cudaFuncAttributeMaxDynamicSharedMemorySize, GSMEM);
    cudaFuncSetAttribute((const void*)gemm_k<1, false>,
                         cudaFuncAttributeMaxDynamicSharedMemorySize, GSMEM);

    // 0) limb split of [W; z], inverse norms, zero counters
    split_norm<<<Nsup, NTHR>>>(z, W, Ah, Am, invn, cnt);

    // 1) merged logits: 128x128 tiles, split-K=4 slices -> separate partial buffers
    gemm_k<3, true><<<dim3(8, 40, SPLITK_N), 256, GSMEM>>>(Ah, Am, Ah, Am, P, Nsup, Cq);

    // 2) warp-per-row: sum partials, entropy + argmax + per-class bucket scatter
    row_entropy_scatter<<<Nsup / 8, NTHR>>>(P, cnt, bktE, bktI);

    // 3) per-class selection (warp per class, read-only, ascending emit)
    select_topk<<<(Cq + (NTHR / 32) - 1) / (NTHR / 32), NTHR>>>(cnt, bktE, bktI, pK,
                                                               selidx, selcnt);

    // 4) prototypes (fp16 high limb only)
    build_weights<<<Cq, NTHR>>>(W, z, invn, selidx, selcnt, Th);

    // 5) out = z @ weights   (single-pair fp16, 128x128 tiles, <1 wave)
    gemm_k<1, false><<<dim3(8, 32), 256, GSMEM>>>(Ah + (size_t)Cq * Dq, Am + (size_t)Cq * Dq,
                                                  Th, Th, out, Bq, Cq);
}